// round 1
// baseline (speedup 1.0000x reference)
#include <cuda_runtime.h>

// RoIMaskAlign: features (B=2, C=256, H=200, W=272) fp32, rois (K, 5) fp32
// out (K, C, 14, 14) fp32
// Constants from the reference:
//   PH=PW=14, SPATIAL_SCALE=0.25, SR=2, SPATIAL_SHIFT=0, HALF_PART=0, ROI_SCALE=1.2

#define PH 14
#define PW 14

static constexpr int   Cc = 256;
static constexpr int   Hc = 200;
static constexpr int   Wc = 272;
static constexpr float SCALE     = 0.25f;
static constexpr float ROI_SCALE = 1.2f;

__global__ __launch_bounds__(256)
void roi_mask_align_kernel(const float* __restrict__ feat,
                           const float* __restrict__ rois,
                           float* __restrict__ out,
                           int total)
{
    int idx = blockIdx.x * blockDim.x + threadIdx.x;
    if (idx >= total) return;

    int pw = idx % PW;
    int t1 = idx / PW;
    int ph = t1 % PH;
    int t2 = t1 / PH;
    int c  = t2 % Cc;
    int n  = t2 / Cc;

    // ROI params: warp-mostly-uniform (whole warp is in one (n,c) plane
    // except at 196-element boundaries) -> cached / broadcast loads.
    const float* r = rois + n * 5;
    int   b  = (int)r[0];
    float x1 = r[1], y1 = r[2], x2 = r[3], y2 = r[4];

    float cx = (x1 + x2) * 0.5f;
    float cy = (y1 + y2) * 0.5f;
    float w  = (x2 - x1) * ROI_SCALE;
    float h  = (y2 - y1) * ROI_SCALE;
    // SPATIAL_SHIFT = 0, HALF_PART = 0: no further adjustment.
    float x1s = (cx - 0.5f * w) * SCALE;
    float x2s = (cx + 0.5f * w) * SCALE;
    float y1s = (cy - 0.5f * h) * SCALE;
    float y2s = (cy + 0.5f * h) * SCALE;

    // Match reference FP order: subtract AFTER scaling.
    float roi_w = fmaxf(x2s - x1s, 1.0f);
    float roi_h = fmaxf(y2s - y1s, 1.0f);
    float bin_w = roi_w * (1.0f / PW);
    float bin_h = roi_h * (1.0f / PH);

    const float* fb = feat + ((size_t)(b * Cc + c)) * (Hc * Wc);

    // Precompute x-sample data (shared across the two sy rows)
    int   x0i[2], x1i[2];
    float lx[2], hx[2];
    bool  vx[2];
    #pragma unroll
    for (int sx = 0; sx < 2; sx++) {
        float x = x1s + ((float)pw + ((float)sx + 0.5f) * 0.5f) * bin_w;
        vx[sx] = (x > -1.0f) && (x < (float)Wc);
        float xc = fminf(fmaxf(x, 0.0f), (float)(Wc - 1));
        int x0 = (int)floorf(xc);
        x0i[sx] = x0;
        x1i[sx] = min(x0 + 1, Wc - 1);
        lx[sx] = xc - (float)x0;
        hx[sx] = 1.0f - lx[sx];
    }

    float sum = 0.0f;
    #pragma unroll
    for (int sy = 0; sy < 2; sy++) {
        float y = y1s + ((float)ph + ((float)sy + 0.5f) * 0.5f) * bin_h;
        bool vy = (y > -1.0f) && (y < (float)Hc);
        float yc = fminf(fmaxf(y, 0.0f), (float)(Hc - 1));
        int y0 = (int)floorf(yc);
        int y1b = min(y0 + 1, Hc - 1);
        float ly = yc - (float)y0;
        float hy = 1.0f - ly;

        const float* row0 = fb + (size_t)y0  * Wc;
        const float* row1 = fb + (size_t)y1b * Wc;

        #pragma unroll
        for (int sx = 0; sx < 2; sx++) {
            if (vy && vx[sx]) {
                float v00 = __ldg(row0 + x0i[sx]);
                float v01 = __ldg(row0 + x1i[sx]);
                float v10 = __ldg(row1 + x0i[sx]);
                float v11 = __ldg(row1 + x1i[sx]);
                sum += (hy * hx[sx]) * v00 + (hy * lx[sx]) * v01
                     + (ly * hx[sx]) * v10 + (ly * lx[sx]) * v11;
            }
        }
    }

    out[idx] = sum * 0.25f;  // mean over SR*SR = 4 samples
}

extern "C" void kernel_launch(void* const* d_in, const int* in_sizes, int n_in,
                              void* d_out, int out_size)
{
    const float* feat = (const float*)d_in[0];
    const float* rois = (const float*)d_in[1];
    float* out = (float*)d_out;

    int total = out_size;  // K * C * PH * PW
    int threads = 256;
    int blocks = (total + threads - 1) / threads;
    roi_mask_align_kernel<<<blocks, threads>>>(feat, rois, out, total);
}